// round 2
// baseline (speedup 1.0000x reference)
#include <cuda_runtime.h>

#define D 64
#define KCHUNK 128
#define TPB 128

// scratch for 0.5*||c_k||^2 precompute (device global: no allocation)
__device__ float g_halfnorm[8192];

__global__ void halfnorm_kernel(const float* __restrict__ centroids, int K) {
    int k = blockIdx.x * blockDim.x + threadIdx.x;
    if (k >= K) return;
    const float4* c = (const float4*)(centroids + (size_t)k * D);
    float s = 0.f;
#pragma unroll
    for (int i = 0; i < D / 4; i++) {
        float4 v = c[i];
        s += v.x * v.x + v.y * v.y + v.z * v.z + v.w * v.w;
    }
    g_halfnorm[k] = 0.5f * s;
}

__device__ __forceinline__ unsigned long long ffma2(unsigned long long a,
                                                    unsigned long long b,
                                                    unsigned long long c) {
    unsigned long long d;
    asm("fma.rn.f32x2 %0, %1, %2, %3;" : "=l"(d) : "l"(a), "l"(b), "l"(c));
    return d;
}
__device__ __forceinline__ unsigned long long pack2(float lo, float hi) {
    unsigned long long r;
    asm("mov.b64 %0, {%1, %2};" : "=l"(r) : "f"(lo), "f"(hi));
    return r;
}
__device__ __forceinline__ float2 unpack2(unsigned long long v) {
    float2 r;
    asm("mov.b64 {%0, %1}, %2;" : "=f"(r.x), "=f"(r.y) : "l"(v));
    return r;
}

// OutMode: 0 = all-float32 buffer: bins (as f32) at [0,N), residual f32 at [N, N+N*D)
//          1 = raw byte concat: int64 bins then float32 residual
template <int OutMode>
__global__ __launch_bounds__(TPB, 4) void vq_kernel(
    const float* __restrict__ action, const float* __restrict__ centroids,
    void* __restrict__ out, int N, int K) {
    __shared__ float sc[KCHUNK * D];   // 32 KB centroid chunk
    __shared__ float shn[KCHUNK];

    const int p = blockIdx.x * TPB + threadIdx.x;

    // Load this thread's action vector into packed f32x2 registers.
    unsigned long long a2[D / 2];
    {
        const float4* ap = (const float4*)(action + (size_t)p * D);
#pragma unroll
        for (int i = 0; i < D / 4; i++) {
            float4 v = ap[i];
            a2[2 * i]     = pack2(v.x, v.y);
            a2[2 * i + 1] = pack2(v.z, v.w);
        }
    }

    float bestScore = -3.402823466e38f;
    int bestK = 0;

    const int nChunks = K / KCHUNK;
    for (int ch = 0; ch < nChunks; ch++) {
        __syncthreads();
        // Cooperative load of KCHUNK centroids (coalesced float4).
        const float4* src = (const float4*)(centroids + (size_t)ch * KCHUNK * D);
        float4* dst = (float4*)sc;
#pragma unroll
        for (int i = 0; i < (KCHUNK * D / 4) / TPB; i++)
            dst[threadIdx.x + i * TPB] = src[threadIdx.x + i * TPB];
        shn[threadIdx.x] = g_halfnorm[ch * KCHUNK + threadIdx.x];  // KCHUNK==TPB
        __syncthreads();

#pragma unroll 2
        for (int kk = 0; kk < KCHUNK; kk++) {
            const ulonglong2* cp = (const ulonglong2*)&sc[kk * D];
            // score = a . c_k - 0.5*||c_k||^2  (argmax == argmin of d2)
            unsigned long long acc0 = pack2(-shn[kk], 0.f);
            unsigned long long acc1 = pack2(0.f, 0.f);
#pragma unroll
            for (int i = 0; i < D / 4; i++) {
                ulonglong2 c = cp[i];
                acc0 = ffma2(a2[2 * i], c.x, acc0);
                acc1 = ffma2(a2[2 * i + 1], c.y, acc1);
            }
            float2 f0 = unpack2(acc0), f1 = unpack2(acc1);
            float s = (f0.x + f1.x) + (f0.y + f1.y);
            if (s > bestScore) {   // strict > keeps earliest index (argmin tie rule)
                bestScore = s;
                bestK = ch * KCHUNK + kk;
            }
        }
    }

    // Epilogue: write bin + residual.
    const float* cbest = centroids + (size_t)bestK * D;
    if (OutMode == 1) {
        ((long long*)out)[p] = (long long)bestK;
        float* rout = (float*)out + 2 * (size_t)N + (size_t)p * D;
#pragma unroll
        for (int i = 0; i < D / 2; i++) {
            float2 a = unpack2(a2[i]);
            rout[2 * i]     = a.x - cbest[2 * i];
            rout[2 * i + 1] = a.y - cbest[2 * i + 1];
        }
    } else {
        float* o = (float*)out;
        o[p] = (float)bestK;                       // bins as f32 (exact for K<=2048)
        float* rout = o + (size_t)N + (size_t)p * D;
#pragma unroll
        for (int i = 0; i < D / 2; i++) {
            float2 a = unpack2(a2[i]);
            rout[2 * i]     = a.x - cbest[2 * i];
            rout[2 * i + 1] = a.y - cbest[2 * i + 1];
        }
    }
}

extern "C" void kernel_launch(void* const* d_in, const int* in_sizes, int n_in,
                              void* d_out, int out_size) {
    const float* action = (const float*)d_in[0];
    const float* centroids = (const float*)d_in[1];
    const int N = in_sizes[0] / D;   // 65536
    const int K = in_sizes[1] / D;   // 2048

    halfnorm_kernel<<<(K + 127) / 128, 128>>>(centroids, K);

    const int grid = N / TPB;
    const long long os = (long long)out_size;
    // Layout detection:
    //   N*(D+1) elements  -> single float32 buffer (JAX promotion: i64+f32 -> f32)
    //   N*(D+2) elements  -> byte layout counted in f32: int64 bins + f32 residual
    //   N*(D/2+1) elems   -> byte layout counted in int64: same byte layout
    if (os == (long long)N * (D + 2) || os == (long long)N * (D / 2 + 1)) {
        vq_kernel<1><<<grid, TPB>>>(action, centroids, d_out, N, K);
    } else {
        vq_kernel<0><<<grid, TPB>>>(action, centroids, d_out, N, K);
    }
}

// round 3
// speedup vs baseline: 1.2764x; 1.2764x over previous
#include <cuda_runtime.h>

#define D 64
#define KCHUNK 128
#define TPB 256
#define P 2   // points per thread

// scratch for 0.5*||c_k||^2 precompute (device global: no allocation)
__device__ float g_halfnorm[8192];

__global__ void halfnorm_kernel(const float* __restrict__ centroids, int K) {
    int k = blockIdx.x * blockDim.x + threadIdx.x;
    if (k >= K) return;
    const float4* c = (const float4*)(centroids + (size_t)k * D);
    float s = 0.f;
#pragma unroll
    for (int i = 0; i < D / 4; i++) {
        float4 v = c[i];
        s += v.x * v.x + v.y * v.y + v.z * v.z + v.w * v.w;
    }
    g_halfnorm[k] = 0.5f * s;
}

__device__ __forceinline__ unsigned long long ffma2(unsigned long long a,
                                                    unsigned long long b,
                                                    unsigned long long c) {
    unsigned long long d;
    asm("fma.rn.f32x2 %0, %1, %2, %3;" : "=l"(d) : "l"(a), "l"(b), "l"(c));
    return d;
}
__device__ __forceinline__ unsigned long long pack2(float lo, float hi) {
    unsigned long long r;
    asm("mov.b64 %0, {%1, %2};" : "=l"(r) : "f"(lo), "f"(hi));
    return r;
}
__device__ __forceinline__ float2 unpack2(unsigned long long v) {
    float2 r;
    asm("mov.b64 {%0, %1}, %2;" : "=f"(r.x), "=f"(r.y) : "l"(v));
    return r;
}

// OutMode: 0 = all-float32 buffer: bins (as f32) at [0,N), residual f32 at [N, N+N*D)
//          1 = raw byte concat: int64 bins then float32 residual
template <int OutMode>
__global__ __launch_bounds__(TPB, 1) void vq_kernel(
    const float* __restrict__ action, const float* __restrict__ centroids,
    void* __restrict__ out, int N, int K) {
    __shared__ float sc[KCHUNK * D];   // 32 KB centroid chunk
    __shared__ float shn[KCHUNK];

    // Two points per thread: p[0] = base+tid, p[1] = base+tid+TPB (coalesced-ish)
    const int pbase = blockIdx.x * (TPB * P) + threadIdx.x;

    unsigned long long a2[P][D / 2];
#pragma unroll
    for (int j = 0; j < P; j++) {
        const float4* ap = (const float4*)(action + (size_t)(pbase + j * TPB) * D);
#pragma unroll
        for (int i = 0; i < D / 4; i++) {
            float4 v = ap[i];
            a2[j][2 * i]     = pack2(v.x, v.y);
            a2[j][2 * i + 1] = pack2(v.z, v.w);
        }
    }

    float bestScore[P];
    int bestK[P];
#pragma unroll
    for (int j = 0; j < P; j++) { bestScore[j] = -3.402823466e38f; bestK[j] = 0; }

    const int nChunks = K / KCHUNK;
    for (int ch = 0; ch < nChunks; ch++) {
        __syncthreads();
        // Cooperative load of KCHUNK centroids (coalesced float4): 8192 floats.
        const float4* src = (const float4*)(centroids + (size_t)ch * KCHUNK * D);
        float4* dst = (float4*)sc;
#pragma unroll
        for (int i = 0; i < (KCHUNK * D / 4) / TPB; i++)
            dst[threadIdx.x + i * TPB] = src[threadIdx.x + i * TPB];
        if (threadIdx.x < KCHUNK)
            shn[threadIdx.x] = g_halfnorm[ch * KCHUNK + threadIdx.x];
        __syncthreads();

#pragma unroll 2
        for (int kk = 0; kk < KCHUNK; kk++) {
            const ulonglong2* cp = (const ulonglong2*)&sc[kk * D];
            const float nh = -shn[kk];
            // score = a . c_k - 0.5*||c_k||^2  (argmax == argmin of d2)
            unsigned long long acc0[P], acc1[P];
#pragma unroll
            for (int j = 0; j < P; j++) {
                acc0[j] = pack2(nh, 0.f);
                acc1[j] = pack2(0.f, 0.f);
            }
#pragma unroll
            for (int i = 0; i < D / 4; i++) {
                ulonglong2 c = cp[i];
#pragma unroll
                for (int j = 0; j < P; j++) {
                    acc0[j] = ffma2(a2[j][2 * i], c.x, acc0[j]);
                    acc1[j] = ffma2(a2[j][2 * i + 1], c.y, acc1[j]);
                }
            }
#pragma unroll
            for (int j = 0; j < P; j++) {
                float2 f0 = unpack2(acc0[j]), f1 = unpack2(acc1[j]);
                float s = (f0.x + f1.x) + (f0.y + f1.y);
                if (s > bestScore[j]) {   // strict > keeps earliest index
                    bestScore[j] = s;
                    bestK[j] = ch * KCHUNK + kk;
                }
            }
        }
    }

    // Epilogue: write bin + residual for both points.
#pragma unroll
    for (int j = 0; j < P; j++) {
        const int p = pbase + j * TPB;
        const float* cbest = centroids + (size_t)bestK[j] * D;
        if (OutMode == 1) {
            ((long long*)out)[p] = (long long)bestK[j];
            float* rout = (float*)out + 2 * (size_t)N + (size_t)p * D;
#pragma unroll
            for (int i = 0; i < D / 2; i++) {
                float2 a = unpack2(a2[j][i]);
                rout[2 * i]     = a.x - cbest[2 * i];
                rout[2 * i + 1] = a.y - cbest[2 * i + 1];
            }
        } else {
            float* o = (float*)out;
            o[p] = (float)bestK[j];            // bins as f32 (exact for K<=2048)
            float* rout = o + (size_t)N + (size_t)p * D;
#pragma unroll
            for (int i = 0; i < D / 2; i++) {
                float2 a = unpack2(a2[j][i]);
                rout[2 * i]     = a.x - cbest[2 * i];
                rout[2 * i + 1] = a.y - cbest[2 * i + 1];
            }
        }
    }
}

extern "C" void kernel_launch(void* const* d_in, const int* in_sizes, int n_in,
                              void* d_out, int out_size) {
    const float* action = (const float*)d_in[0];
    const float* centroids = (const float*)d_in[1];
    const int N = in_sizes[0] / D;   // 65536
    const int K = in_sizes[1] / D;   // 2048

    halfnorm_kernel<<<(K + 127) / 128, 128>>>(centroids, K);

    const int grid = N / (TPB * P);  // 128 CTAs -> 1 per SM
    const long long os = (long long)out_size;
    if (os == (long long)N * (D + 2) || os == (long long)N * (D / 2 + 1)) {
        vq_kernel<1><<<grid, TPB>>>(action, centroids, d_out, N, K);
    } else {
        vq_kernel<0><<<grid, TPB>>>(action, centroids, d_out, N, K);
    }
}

// round 6
// speedup vs baseline: 1.7217x; 1.3489x over previous
#include <cuda_runtime.h>
#include <cstdint>

#define D 64
#define KTOT 2048
#define MTILE 128
#define NCHUNK 128
#define NCHUNKS (KTOT / NCHUNK)   // 16
#define TPB 256

#define SA 68            // A smem row stride (f32)
#define SB 132           // B smem row stride (float2)

#define OFF_A  0
#define A_BYTES (MTILE * SA * 4)              // 34816
#define OFF_B0 (OFF_A + A_BYTES)
#define B_BYTES (D * SB * 8)                  // 67584
#define OFF_B1 (OFF_B0 + B_BYTES)
#define OFF_HN (OFF_B1 + B_BYTES)             // 2048 f32
#define OFF_BK (OFF_HN + KTOT * 4)            // 128 int
#define SMEM_TOTAL (OFF_BK + MTILE * 4)       // 178,688 B

// ---------------- device scratch (no runtime allocation) ----------------
__device__ float g_halfnorm[KTOT];
__device__ __align__(16) float2 g_bsplit[NCHUNKS * D * NCHUNK];  // [chunk][k][n] = (hi,lo) tf32

// ---------------- helpers ----------------
__device__ __forceinline__ uint32_t smem_u32(const void* p) {
    uint32_t a;
    asm("{ .reg .u64 t; cvta.to.shared.u64 t, %1; cvt.u32.u64 %0, t; }" : "=r"(a) : "l"(p));
    return a;
}
__device__ __forceinline__ uint32_t f2tf32(float x) {
    uint32_t r;
    asm("cvt.rna.tf32.f32 %0, %1;" : "=r"(r) : "f"(x));
    return r;
}
__device__ __forceinline__ void mma_tf32(float& c0, float& c1, float& c2, float& c3,
                                         uint32_t a0, uint32_t a1, uint32_t a2, uint32_t a3,
                                         uint32_t b0, uint32_t b1) {
    asm volatile(
        "mma.sync.aligned.m16n8k8.row.col.f32.tf32.tf32.f32 "
        "{%0,%1,%2,%3}, {%4,%5,%6,%7}, {%8,%9}, {%0,%1,%2,%3};"
        : "+f"(c0), "+f"(c1), "+f"(c2), "+f"(c3)
        : "r"(a0), "r"(a1), "r"(a2), "r"(a3), "r"(b0), "r"(b1));
}
#define CP_ASYNC16(dst, src) \
    asm volatile("cp.async.cg.shared.global [%0], [%1], 16;" :: "r"(dst), "l"(src) : "memory")
#define CP_COMMIT() asm volatile("cp.async.commit_group;" ::: "memory")
#define CP_WAIT1()  asm volatile("cp.async.wait_group 1;" ::: "memory")

// ---------------- prep kernels ----------------
__global__ void halfnorm_kernel(const float* __restrict__ centroids) {
    int k = blockIdx.x * blockDim.x + threadIdx.x;
    if (k >= KTOT) return;
    const float4* c = (const float4*)(centroids + (size_t)k * D);
    float s = 0.f;
#pragma unroll
    for (int i = 0; i < D / 4; i++) {
        float4 v = c[i];
        s += v.x * v.x + v.y * v.y + v.z * v.z + v.w * v.w;
    }
    g_halfnorm[k] = 0.5f * s;
}

__global__ void split_centroids_kernel(const float* __restrict__ c) {
    int idx = blockIdx.x * blockDim.x + threadIdx.x;
    if (idx >= KTOT * D) return;
    int kc = idx / D, dd = idx % D;
    float x = c[idx];
    uint32_t hi = f2tf32(x);
    uint32_t lo = f2tf32(x - __uint_as_float(hi));
    int chunk = kc >> 7, n = kc & 127;
    g_bsplit[((size_t)chunk * D + dd) * NCHUNK + n] =
        make_float2(__uint_as_float(hi), __uint_as_float(lo));
}

// ---------------- main kernel ----------------
__device__ __forceinline__ void prefetch_chunk(uint32_t sb_smem, int buf, int ch, int tid) {
    // 64 rows x 128 float2 = 64 KB = 4096 uint4; smem row stride 1056 B
    const char* src = (const char*)g_bsplit + (size_t)ch * 65536;
#pragma unroll
    for (int i = 0; i < 16; i++) {
        int idx = tid + i * TPB;           // 0..4095
        int r = idx >> 6, u = idx & 63;
        uint32_t dst = sb_smem + (buf ? OFF_B1 : OFF_B0) + r * (SB * 8) + u * 16;
        CP_ASYNC16(dst, src + r * 1024 + u * 16);
    }
}

template <int OutMode>
__global__ __launch_bounds__(TPB) void vq_mma_kernel(
    const float* __restrict__ action, const float* __restrict__ centroids,
    void* __restrict__ out, int N) {
    extern __shared__ char smem[];
    const uint32_t sbm = smem_u32(smem);
    const int tid = threadIdx.x;
    const int w = tid >> 5;
    const int lane = tid & 31;
    const int g = lane >> 2;     // group id 0..7
    const int t = lane & 3;      // thread-in-group 0..3

    // prefetch first two B chunks
    prefetch_chunk(sbm, 0, 0, tid);
    CP_COMMIT();
    prefetch_chunk(sbm, 1, 1, tid);
    CP_COMMIT();

    // stage A tile [128][64] -> padded smem
    {
        const float4* src = (const float4*)(action + (size_t)blockIdx.x * MTILE * D);
#pragma unroll
        for (int i = 0; i < 8; i++) {
            int idx = tid + i * TPB;        // 2048 float4
            int r = idx >> 4, c4 = idx & 15;
            *(float4*)(smem + OFF_A + r * (SA * 4) + c4 * 16) = src[idx];
        }
    }
    // stage halfnorms
    {
        const float4* src = (const float4*)g_halfnorm;
#pragma unroll
        for (int i = 0; i < 2; i++) {
            int idx = tid + i * TPB;        // 512 float4
            *(float4*)(smem + OFF_HN + idx * 16) = src[idx];
        }
    }
    __syncthreads();

    // load + split A fragments for this warp's 16-row slab (reused all chunks)
    const int r0 = w * 16 + g;
    const int r1 = r0 + 8;
    uint32_t ahi[8][4], alo[8][4];
#pragma unroll
    for (int ks = 0; ks < 8; ks++) {
        int c0 = ks * 8 + t, c1 = c0 + 4;
        float x0 = *(const float*)(smem + OFF_A + (r0 * SA + c0) * 4);
        float x1 = *(const float*)(smem + OFF_A + (r1 * SA + c0) * 4);
        float x2 = *(const float*)(smem + OFF_A + (r0 * SA + c1) * 4);
        float x3 = *(const float*)(smem + OFF_A + (r1 * SA + c1) * 4);
        ahi[ks][0] = f2tf32(x0); alo[ks][0] = f2tf32(x0 - __uint_as_float(ahi[ks][0]));
        ahi[ks][1] = f2tf32(x1); alo[ks][1] = f2tf32(x1 - __uint_as_float(ahi[ks][1]));
        ahi[ks][2] = f2tf32(x2); alo[ks][2] = f2tf32(x2 - __uint_as_float(ahi[ks][2]));
        ahi[ks][3] = f2tf32(x3); alo[ks][3] = f2tf32(x3 - __uint_as_float(ahi[ks][3]));
    }

    float best0 = -3.402823466e38f, best1 = -3.402823466e38f;
    int bk0 = 0, bk1 = 0;

    const uint32_t browoff = (uint32_t)(t * SB + g) * 8;   // byte offset of (k=t, n=g)

    for (int ch = 0; ch < NCHUNKS; ch++) {
        CP_WAIT1();
        __syncthreads();
        const char* bbase = (const char*)smem + ((ch & 1) ? OFF_B1 : OFF_B0) + browoff;
        const float* hn = (const float*)(smem + OFF_HN) + ch * NCHUNK;

#pragma unroll
        for (int ng = 0; ng < 4; ng++) {                 // n-atom groups of 4
            float acc[4][4];
#pragma unroll
            for (int q = 0; q < 4; q++)
#pragma unroll
                for (int j = 0; j < 4; j++) acc[q][j] = 0.f;

#pragma unroll
            for (int ks = 0; ks < 8; ks++) {
                float2 bp0[4], bp1[4];
#pragma unroll
                for (int q = 0; q < 4; q++) {
                    const char* p0 = bbase + (uint32_t)ks * (8 * SB * 8) +
                                     (uint32_t)(ng * 32 + q * 8) * 8;
                    bp0[q] = *(const float2*)p0;                 // k = 8ks+t,   n = n0+g
                    bp1[q] = *(const float2*)(p0 + 4 * SB * 8);  // k = 8ks+t+4, n = n0+g
                }
#pragma unroll
                for (int q = 0; q < 4; q++) {
                    uint32_t bh0 = __float_as_uint(bp0[q].x), bl0 = __float_as_uint(bp0[q].y);
                    uint32_t bh1 = __float_as_uint(bp1[q].x), bl1 = __float_as_uint(bp1[q].y);
                    mma_tf32(acc[q][0], acc[q][1], acc[q][2], acc[q][3],
                             ahi[ks][0], ahi[ks][1], ahi[ks][2], ahi[ks][3], bh0, bh1);
                    mma_tf32(acc[q][0], acc[q][1], acc[q][2], acc[q][3],
                             ahi[ks][0], ahi[ks][1], ahi[ks][2], ahi[ks][3], bl0, bl1);
                    mma_tf32(acc[q][0], acc[q][1], acc[q][2], acc[q][3],
                             alo[ks][0], alo[ks][1], alo[ks][2], alo[ks][3], bh0, bh1);
                }
            }

            // argmax update (ascending n => strict '>' keeps earliest index)
#pragma unroll
            for (int q = 0; q < 4; q++) {
                const int n0 = ng * 32 + q * 8;
                const int na = n0 + 2 * t, nb = na + 1;
                float hna = hn[na], hnb = hn[nb];
                float s0 = acc[q][0] - hna;           // row r0, col na
                float s1 = acc[q][1] - hnb;           // row r0, col nb
                float s2 = acc[q][2] - hna;           // row r1, col na
                float s3 = acc[q][3] - hnb;           // row r1, col nb
                const int base = ch * NCHUNK;
                if (s0 > best0) { best0 = s0; bk0 = base + na; }
                if (s1 > best0) { best0 = s1; bk0 = base + nb; }
                if (s2 > best1) { best1 = s2; bk1 = base + na; }
                if (s3 > best1) { best1 = s3; bk1 = base + nb; }
            }
        }

        __syncthreads();
        if (ch + 2 < NCHUNKS) prefetch_chunk(sbm, ch & 1, ch + 2, tid);
        CP_COMMIT();
    }

    // reduce across the quad (t = 0..3), earliest index on ties
#pragma unroll
    for (int off = 1; off < 4; off <<= 1) {
        float ob = __shfl_xor_sync(0xffffffffu, best0, off);
        int ok = __shfl_xor_sync(0xffffffffu, bk0, off);
        if (ob > best0 || (ob == best0 && ok < bk0)) { best0 = ob; bk0 = ok; }
        ob = __shfl_xor_sync(0xffffffffu, best1, off);
        ok = __shfl_xor_sync(0xffffffffu, bk1, off);
        if (ob > best1 || (ob == best1 && ok < bk1)) { best1 = ob; bk1 = ok; }
    }
    if (t == 0) {
        ((int*)(smem + OFF_BK))[r0] = bk0;
        ((int*)(smem + OFF_BK))[r1] = bk1;
    }
    __syncthreads();

    // epilogue
    const int* sbk = (const int*)(smem + OFF_BK);
    const int pbase = blockIdx.x * MTILE;
    if (OutMode == 1) {
        if (tid < MTILE) ((long long*)out)[pbase + tid] = (long long)sbk[tid];
        float* rbase = (float*)out + 2 * (size_t)N;
#pragma unroll
        for (int i = 0; i < 8; i++) {
            int idx = tid + i * TPB;
            int row = idx >> 4, c4 = idx & 15;
            float4 a = *(const float4*)(smem + OFF_A + row * (SA * 4) + c4 * 16);
            float4 c = ((const float4*)(centroids + (size_t)sbk[row] * D))[c4];
            ((float4*)(rbase + (size_t)(pbase + row) * D))[c4] =
                make_float4(a.x - c.x, a.y - c.y, a.z - c.z, a.w - c.w);
        }
    } else {
        float* o = (float*)out;
        if (tid < MTILE) o[pbase + tid] = (float)sbk[tid];   // exact for K<=2048
        float* rbase = o + (size_t)N;
#pragma unroll
        for (int i = 0; i < 8; i++) {
            int idx = tid + i * TPB;
            int row = idx >> 4, c4 = idx & 15;
            float4 a = *(const float4*)(smem + OFF_A + row * (SA * 4) + c4 * 16);
            float4 c = ((const float4*)(centroids + (size_t)sbk[row] * D))[c4];
            ((float4*)(rbase + (size_t)(pbase + row) * D))[c4] =
                make_float4(a.x - c.x, a.y - c.y, a.z - c.z, a.w - c.w);
        }
    }
}

// ---------------- launch ----------------
extern "C" void kernel_launch(void* const* d_in, const int* in_sizes, int n_in,
                              void* d_out, int out_size) {
    const float* action = (const float*)d_in[0];
    const float* centroids = (const float*)d_in[1];
    const int N = in_sizes[0] / D;   // 65536

    cudaFuncSetAttribute(vq_mma_kernel<0>, cudaFuncAttributeMaxDynamicSharedMemorySize, SMEM_TOTAL);
    cudaFuncSetAttribute(vq_mma_kernel<1>, cudaFuncAttributeMaxDynamicSharedMemorySize, SMEM_TOTAL);

    halfnorm_kernel<<<(KTOT + 127) / 128, 128>>>(centroids);
    split_centroids_kernel<<<(KTOT * D + 255) / 256, 256>>>(centroids);

    const int grid = N / MTILE;  // 512
    const long long os = (long long)out_size;
    if (os == (long long)N * (D + 2) || os == (long long)N * (D / 2 + 1)) {
        vq_mma_kernel<1><<<grid, TPB, SMEM_TOTAL>>>(action, centroids, d_out, N);
    } else {
        vq_mma_kernel<0><<<grid, TPB, SMEM_TOTAL>>>(action, centroids, d_out, N);
    }
}

// round 7
// speedup vs baseline: 3.4967x; 2.0310x over previous
#include <cuda_runtime.h>
#include <cuda_fp16.h>
#include <cstdint>

#define D 64
#define KTOT 2048
#define MTILE 128
#define NCHUNK 128
#define NCHUNKS (KTOT / NCHUNK)   // 16
#define TPB 256

#define SA 68             // A smem row stride (f32)
#define SBROW 132         // B smem row stride in uint2 (1056 B)

#define OFF_A  0
#define A_BYTES (MTILE * SA * 4)                  // 34816
#define OFF_B0 A_BYTES
#define B_BYTES (32 * SBROW * 8)                  // 33792 (32 k-pair rows)
#define OFF_B1 (OFF_B0 + B_BYTES)                 // 68608
#define OFF_HN (OFF_B1 + B_BYTES)                 // 102400
#define OFF_BK (OFF_HN + KTOT * 4)                // 110592
#define SMEM_TOTAL (OFF_BK + MTILE * 4)           // 111104

// ---------------- device scratch (no runtime allocation) ----------------
__device__ float g_halfnorm[KTOT];
// [chunk][kpair(32)][n(128)] -> (h0|h1<<16, l0|l1<<16)
__device__ __align__(16) uint2 g_bsplit[NCHUNKS * 32 * NCHUNK];

// ---------------- helpers ----------------
__device__ __forceinline__ uint32_t smem_u32(const void* p) {
    uint32_t a;
    asm("{ .reg .u64 t; cvta.to.shared.u64 t, %1; cvt.u32.u64 %0, t; }" : "=r"(a) : "l"(p));
    return a;
}
__device__ __forceinline__ void split_f16(float x, uint16_t& h, uint16_t& l) {
    __half hh = __float2half_rn(x);
    __half ll = __float2half_rn(x - __half2float(hh));
    h = __half_as_ushort(hh);
    l = __half_as_ushort(ll);
}
__device__ __forceinline__ void mma_f16(float& c0, float& c1, float& c2, float& c3,
                                        uint32_t a0, uint32_t a1, uint32_t a2, uint32_t a3,
                                        uint32_t b0, uint32_t b1) {
    asm volatile(
        "mma.sync.aligned.m16n8k16.row.col.f32.f16.f16.f32 "
        "{%0,%1,%2,%3}, {%4,%5,%6,%7}, {%8,%9}, {%0,%1,%2,%3};"
        : "+f"(c0), "+f"(c1), "+f"(c2), "+f"(c3)
        : "r"(a0), "r"(a1), "r"(a2), "r"(a3), "r"(b0), "r"(b1));
}
#define CP_ASYNC16(dst, src) \
    asm volatile("cp.async.cg.shared.global [%0], [%1], 16;" :: "r"(dst), "l"(src) : "memory")
#define CP_COMMIT() asm volatile("cp.async.commit_group;" ::: "memory")
#define CP_WAIT1()  asm volatile("cp.async.wait_group 1;" ::: "memory")

// ---------------- prep kernels ----------------
__global__ void halfnorm_kernel(const float* __restrict__ centroids) {
    int k = blockIdx.x * blockDim.x + threadIdx.x;
    if (k >= KTOT) return;
    const float4* c = (const float4*)(centroids + (size_t)k * D);
    float s = 0.f;
#pragma unroll
    for (int i = 0; i < D / 4; i++) {
        float4 v = c[i];
        s += v.x * v.x + v.y * v.y + v.z * v.z + v.w * v.w;
    }
    g_halfnorm[k] = 0.5f * s;
}

__global__ void split_centroids_kernel(const float* __restrict__ c) {
    int idx = blockIdx.x * blockDim.x + threadIdx.x;
    if (idx >= KTOT * 32) return;
    int kc = idx >> 5, kp = idx & 31;
    float x0 = c[kc * D + 2 * kp];
    float x1 = c[kc * D + 2 * kp + 1];
    uint16_t h0, l0, h1, l1;
    split_f16(x0, h0, l0);
    split_f16(x1, h1, l1);
    int chunk = kc >> 7, n = kc & 127;
    g_bsplit[chunk * (32 * NCHUNK) + kp * NCHUNK + n] =
        make_uint2((uint32_t)h0 | ((uint32_t)h1 << 16),
                   (uint32_t)l0 | ((uint32_t)l1 << 16));
}

// ---------------- main kernel ----------------
__device__ __forceinline__ void prefetch_chunk(uint32_t sbm, int buf, int ch, int tid) {
    // 32 rows x 128 uint2 = 32 KB = 2048 x 16B
    const char* src = (const char*)g_bsplit + (size_t)ch * 32768;
#pragma unroll
    for (int i = 0; i < 8; i++) {
        int idx = tid + i * TPB;           // 0..2047
        int r = idx >> 6, u = idx & 63;
        uint32_t dst = sbm + (buf ? OFF_B1 : OFF_B0) + r * (SBROW * 8) + u * 16;
        CP_ASYNC16(dst, src + r * 1024 + u * 16);
    }
}

template <int OutMode>
__global__ __launch_bounds__(TPB, 2) void vq_mma_kernel(
    const float* __restrict__ action, const float* __restrict__ centroids,
    void* __restrict__ out, int N) {
    extern __shared__ char smem[];
    const uint32_t sbm = smem_u32(smem);
    const int tid = threadIdx.x;
    const int w = tid >> 5;
    const int lane = tid & 31;
    const int g = lane >> 2;     // group id 0..7
    const int t = lane & 3;      // thread-in-group 0..3

    prefetch_chunk(sbm, 0, 0, tid);
    CP_COMMIT();
    prefetch_chunk(sbm, 1, 1, tid);
    CP_COMMIT();

    // stage A tile [128][64] fp32 -> padded smem
    {
        const float4* src = (const float4*)(action + (size_t)blockIdx.x * MTILE * D);
#pragma unroll
        for (int i = 0; i < 8; i++) {
            int idx = tid + i * TPB;
            int r = idx >> 4, c4 = idx & 15;
            *(float4*)(smem + OFF_A + r * (SA * 4) + c4 * 16) = src[idx];
        }
    }
    // stage halfnorms
    {
        const float4* src = (const float4*)g_halfnorm;
#pragma unroll
        for (int i = 0; i < 2; i++) {
            int idx = tid + i * TPB;
            *(float4*)(smem + OFF_HN + idx * 16) = src[idx];
        }
    }
    __syncthreads();

    // A fragments (fp16 h/l split), reused across all chunks.
    // m16n8k16: a0={r0, k 2t,2t+1}, a1={r1, same}, a2={r0, k 2t+8,2t+9}, a3={r1, same}
    const int r0 = w * 16 + g;
    const int r1 = r0 + 8;
    uint32_t ah[4][4], al[4][4];
#pragma unroll
    for (int ks = 0; ks < 4; ks++) {
        const int cb = ks * 16 + 2 * t;
#pragma unroll
        for (int half = 0; half < 2; half++) {      // k-subgroup: +0 / +8
            float2 x0 = *(const float2*)(smem + OFF_A + (r0 * SA + cb + 8 * half) * 4);
            float2 x1 = *(const float2*)(smem + OFF_A + (r1 * SA + cb + 8 * half) * 4);
            uint16_t h0a, l0a, h0b, l0b, h1a, l1a, h1b, l1b;
            split_f16(x0.x, h0a, l0a); split_f16(x0.y, h0b, l0b);
            split_f16(x1.x, h1a, l1a); split_f16(x1.y, h1b, l1b);
            ah[ks][0 + 2 * half] = (uint32_t)h0a | ((uint32_t)h0b << 16);
            al[ks][0 + 2 * half] = (uint32_t)l0a | ((uint32_t)l0b << 16);
            ah[ks][1 + 2 * half] = (uint32_t)h1a | ((uint32_t)h1b << 16);
            al[ks][1 + 2 * half] = (uint32_t)l1a | ((uint32_t)l1b << 16);
        }
    }

    float best0 = -3.402823466e38f, best1 = -3.402823466e38f;
    int bk0 = 0, bk1 = 0;

    const uint32_t browoff = (uint32_t)(t * SBROW + g) * 8;   // (kpair=t, n=g)

    for (int ch = 0; ch < NCHUNKS; ch++) {
        CP_WAIT1();
        __syncthreads();
        const char* bbase = (const char*)smem + ((ch & 1) ? OFF_B1 : OFF_B0) + browoff;
        const float* hn = (const float*)(smem + OFF_HN) + ch * NCHUNK;

#pragma unroll
        for (int ng = 0; ng < 4; ng++) {
            float accH[4][4], accL[4][4];
#pragma unroll
            for (int q = 0; q < 4; q++)
#pragma unroll
                for (int j = 0; j < 4; j++) { accH[q][j] = 0.f; accL[q][j] = 0.f; }

#pragma unroll
            for (int ks = 0; ks < 4; ks++) {
                uint2 u0[4], u1[4];
#pragma unroll
                for (int q = 0; q < 4; q++) {
                    const char* p0 = bbase + (uint32_t)ks * (8 * SBROW * 8) +
                                     (uint32_t)(ng * 32 + q * 8) * 8;
                    u0[q] = *(const uint2*)p0;                      // kpair 8ks+t
                    u1[q] = *(const uint2*)(p0 + 4 * SBROW * 8);    // kpair 8ks+t+4
                }
#pragma unroll
                for (int q = 0; q < 4; q++) {
                    mma_f16(accH[q][0], accH[q][1], accH[q][2], accH[q][3],
                            ah[ks][0], ah[ks][1], ah[ks][2], ah[ks][3], u0[q].x, u1[q].x);
                    mma_f16(accL[q][0], accL[q][1], accL[q][2], accL[q][3],
                            ah[ks][0], ah[ks][1], ah[ks][2], ah[ks][3], u0[q].y, u1[q].y);
                    mma_f16(accL[q][0], accL[q][1], accL[q][2], accL[q][3],
                            al[ks][0], al[ks][1], al[ks][2], al[ks][3], u0[q].x, u1[q].x);
                }
            }

#pragma unroll
            for (int q = 0; q < 4; q++) {
                const int n0 = ng * 32 + q * 8;
                const int na = n0 + 2 * t, nb = na + 1;
                float hna = hn[na], hnb = hn[nb];
                float s0 = (accH[q][0] + accL[q][0]) - hna;   // row r0, col na
                float s1 = (accH[q][1] + accL[q][1]) - hnb;   // row r0, col nb
                float s2 = (accH[q][2] + accL[q][2]) - hna;   // row r1, col na
                float s3 = (accH[q][3] + accL[q][3]) - hnb;   // row r1, col nb
                const int base = ch * NCHUNK;
                if (s0 > best0) { best0 = s0; bk0 = base + na; }
                if (s1 > best0) { best0 = s1; bk0 = base + nb; }
                if (s2 > best1) { best1 = s2; bk1 = base + na; }
                if (s3 > best1) { best1 = s3; bk1 = base + nb; }
            }
        }

        __syncthreads();
        if (ch + 2 < NCHUNKS) prefetch_chunk(sbm, ch & 1, ch + 2, tid);
        CP_COMMIT();
    }

    // quad reduction, earliest index on ties
#pragma unroll
    for (int off = 1; off < 4; off <<= 1) {
        float ob = __shfl_xor_sync(0xffffffffu, best0, off);
        int ok = __shfl_xor_sync(0xffffffffu, bk0, off);
        if (ob > best0 || (ob == best0 && ok < bk0)) { best0 = ob; bk0 = ok; }
        ob = __shfl_xor_sync(0xffffffffu, best1, off);
        ok = __shfl_xor_sync(0xffffffffu, bk1, off);
        if (ob > best1 || (ob == best1 && ok < bk1)) { best1 = ob; bk1 = ok; }
    }
    if (t == 0) {
        ((int*)(smem + OFF_BK))[r0] = bk0;
        ((int*)(smem + OFF_BK))[r1] = bk1;
    }
    __syncthreads();

    // epilogue
    const int* sbk = (const int*)(smem + OFF_BK);
    const int pbase = blockIdx.x * MTILE;
    if (OutMode == 1) {
        if (tid < MTILE) ((long long*)out)[pbase + tid] = (long long)sbk[tid];
        float* rbase = (float*)out + 2 * (size_t)N;
#pragma unroll
        for (int i = 0; i < 8; i++) {
            int idx = tid + i * TPB;
            int row = idx >> 4, c4 = idx & 15;
            float4 a = *(const float4*)(smem + OFF_A + row * (SA * 4) + c4 * 16);
            float4 c = ((const float4*)(centroids + (size_t)sbk[row] * D))[c4];
            ((float4*)(rbase + (size_t)(pbase + row) * D))[c4] =
                make_float4(a.x - c.x, a.y - c.y, a.z - c.z, a.w - c.w);
        }
    } else {
        float* o = (float*)out;
        if (tid < MTILE) o[pbase + tid] = (float)sbk[tid];   // exact for K<=2048
        float* rbase = o + (size_t)N;
#pragma unroll
        for (int i = 0; i < 8; i++) {
            int idx = tid + i * TPB;
            int row = idx >> 4, c4 = idx & 15;
            float4 a = *(const float4*)(smem + OFF_A + row * (SA * 4) + c4 * 16);
            float4 c = ((const float4*)(centroids + (size_t)sbk[row] * D))[c4];
            ((float4*)(rbase + (size_t)(pbase + row) * D))[c4] =
                make_float4(a.x - c.x, a.y - c.y, a.z - c.z, a.w - c.w);
        }
    }
}

// ---------------- launch ----------------
extern "C" void kernel_launch(void* const* d_in, const int* in_sizes, int n_in,
                              void* d_out, int out_size) {
    const float* action = (const float*)d_in[0];
    const float* centroids = (const float*)d_in[1];
    const int N = in_sizes[0] / D;   // 65536

    cudaFuncSetAttribute(vq_mma_kernel<0>, cudaFuncAttributeMaxDynamicSharedMemorySize, SMEM_TOTAL);
    cudaFuncSetAttribute(vq_mma_kernel<1>, cudaFuncAttributeMaxDynamicSharedMemorySize, SMEM_TOTAL);

    halfnorm_kernel<<<(KTOT + 127) / 128, 128>>>(centroids);
    split_centroids_kernel<<<(KTOT * 32 + 255) / 256, 256>>>(centroids);

    const int grid = N / MTILE;  // 512
    const long long os = (long long)out_size;
    if (os == (long long)N * (D + 2) || os == (long long)N * (D / 2 + 1)) {
        vq_mma_kernel<1><<<grid, TPB, SMEM_TOTAL>>>(action, centroids, d_out, N);
    } else {
        vq_mma_kernel<0><<<grid, TPB, SMEM_TOTAL>>>(action, centroids, d_out, N);
    }
}